// round 1
// baseline (speedup 1.0000x reference)
#include <cuda_runtime.h>
#include <math.h>

// Problem constants
#define PB_N0 2048
#define PB_N1 32768
#define PB_N2 524288
#define PB_C  16
#define PB_D  128
#define PB_H  128
#define PB_ED 8

// ---------------- scratch (device globals; no runtime allocation) ----------
__device__ float g_h2[(size_t)PB_N2 * PB_H];      // 268 MB
__device__ float g_M [(size_t)PB_N2 * PB_H];      // 268 MB (reused at level 0)
__device__ float g_pooled[(size_t)PB_N1 * PB_H];  // 16.8 MB (reused at level 0)
__device__ float g_h1[(size_t)PB_N1 * PB_H];      // 16.8 MB
__device__ float g_Wc[3 * PB_D * PB_H];           // W_fe @ W_x[l][:128]
__device__ float g_bias[3 * PB_H];                // b_fe @ W_x[l][:128] + b_r[l]

// ---------------- prep: Wc[l] = W_fe @ W_x[l][0:128,:] ---------------------
__global__ void prep_wc(const float* __restrict__ W_fe,
                        const float* __restrict__ W_x) {
    int l = blockIdx.x >> 7;
    int d = blockIdx.x & 127;
    int h = threadIdx.x;
    const float* wx = W_x + (size_t)l * 132 * 128;
    float acc = 0.f;
    #pragma unroll 8
    for (int k = 0; k < 128; ++k)
        acc += W_fe[d * 128 + k] * wx[k * 128 + h];
    g_Wc[((size_t)l * 128 + d) * 128 + h] = acc;
}

__global__ void prep_bias(const float* __restrict__ b_fe,
                          const float* __restrict__ W_x,
                          const float* __restrict__ b_r) {
    int l = blockIdx.x;
    int h = threadIdx.x;
    const float* wx = W_x + (size_t)l * 132 * 128;
    float acc = b_r[l * 128 + h];
    #pragma unroll 8
    for (int d = 0; d < 128; ++d)
        acc += b_fe[d] * wx[d * 128 + h];
    g_bias[l * 128 + h] = acc;
}

// ---------------- edge-gated mixing: M[p,c,:] = sum_k A*sig(E.We) * ch[k,:]
__global__ __launch_bounds__(256)
void gnn_gate(const float* __restrict__ A, const float* __restrict__ E,
              const float* __restrict__ We, const float* __restrict__ childh,
              float* __restrict__ M) {
    __shared__ float ch[PB_C][PB_H];
    __shared__ float G[PB_C][PB_C];
    size_t p = blockIdx.x;
    int t = threadIdx.x;

    // load 16 child hidden rows (16x128) into smem
    {
        int r = t >> 4;
        int cp = (t & 15) * 8;
        const float* src = childh + ((size_t)p * PB_C + r) * PB_H + cp;
        float4 v0 = *(const float4*)(src);
        float4 v1 = *(const float4*)(src + 4);
        *(float4*)&ch[r][cp]     = v0;
        *(float4*)&ch[r][cp + 4] = v1;
    }
    // gates: G[c][k] = A[p,c,k] * sigmoid(E[p,c,k,:] . We)
    {
        int c = t >> 4, k = t & 15;
        const float* e = E + (((size_t)p * PB_C + c) * PB_C + k) * PB_ED;
        float s = 0.f;
        #pragma unroll
        for (int i = 0; i < PB_ED; ++i) s += e[i] * We[i];
        float g = 1.f / (1.f + __expf(-s));
        G[c][k] = A[((size_t)p * PB_C + c) * PB_C + k] * g;
    }
    __syncthreads();
    // M[p,c,:] = sum_k G[c][k] * ch[k][:]
    {
        int c = t >> 4;
        int cp = (t & 15) * 8;
        float acc[8];
        #pragma unroll
        for (int u = 0; u < 8; ++u) acc[u] = 0.f;
        #pragma unroll
        for (int k = 0; k < PB_C; ++k) {
            float g = G[c][k];
            #pragma unroll
            for (int u = 0; u < 8; ++u) acc[u] += g * ch[k][cp + u];
        }
        float* dst = M + ((size_t)p * PB_C + c) * PB_H + cp;
        *(float4*)(dst)     = make_float4(acc[0], acc[1], acc[2], acc[3]);
        *(float4*)(dst + 4) = make_float4(acc[4], acc[5], acc[6], acc[7]);
    }
}

// ---------------- fused GEMM: [rows,128] @ [128,128] (1 or 2 K-segments) ---
// mode 0: out[row,:] = tanh(A0@W0 (+ A1@W1) + bias + ta[tvec[row]])
// mode 1: pooled[g,:] = max over 16 rows of relu(A0@W0 + bias); 8 parents/blk
__global__ __launch_bounds__(256, 2)
void gemm_fused(const float* __restrict__ A0, const float* __restrict__ W0,
                const float* __restrict__ A1, const float* __restrict__ W1,
                const float* __restrict__ bias, const float* __restrict__ ta,
                const int* __restrict__ tvec, float* __restrict__ out,
                int mode) {
    __shared__ float Xs[16][132];   // transposed x chunk [k][row]
    __shared__ float Ws[16][128];   // weight chunk [k][col]
    int t = threadIdx.x;
    int ti = t & 15, tj = t >> 4;   // 16x16 thread grid
    size_t rowbase = (size_t)blockIdx.x * 128;

    float acc[8][8];
    #pragma unroll
    for (int u = 0; u < 8; ++u)
        #pragma unroll
        for (int v = 0; v < 8; ++v) acc[u][v] = 0.f;

    int nseg = (A1 != nullptr) ? 2 : 1;
    for (int seg = 0; seg < nseg; ++seg) {
        const float* A = seg ? A1 : A0;
        const float* W = seg ? W1 : W0;
        for (int kb = 0; kb < 128; kb += 16) {
            // global loads into regs first (latency overlap)
            int xr = t >> 1;
            int xk = (t & 1) * 8;
            const float* xsrc = A + (rowbase + xr) * 128 + kb + xk;
            float4 xv0 = *(const float4*)(xsrc);
            float4 xv1 = *(const float4*)(xsrc + 4);
            int wk = t >> 4, wc = (t & 15) * 8;
            const float* wsrc = W + (size_t)(kb + wk) * 128 + wc;
            float4 wv0 = *(const float4*)(wsrc);
            float4 wv1 = *(const float4*)(wsrc + 4);
            __syncthreads();   // previous tile fully consumed
            Xs[xk + 0][xr] = xv0.x; Xs[xk + 1][xr] = xv0.y;
            Xs[xk + 2][xr] = xv0.z; Xs[xk + 3][xr] = xv0.w;
            Xs[xk + 4][xr] = xv1.x; Xs[xk + 5][xr] = xv1.y;
            Xs[xk + 6][xr] = xv1.z; Xs[xk + 7][xr] = xv1.w;
            *(float4*)&Ws[wk][wc]     = wv0;
            *(float4*)&Ws[wk][wc + 4] = wv1;
            __syncthreads();
            #pragma unroll
            for (int kk = 0; kk < 16; ++kk) {
                float a[8], b[8];
                // split row fragment: rows ti*4..+3 and 64+ti*4..+3
                *(float4*)&a[0] = *(const float4*)&Xs[kk][ti * 4];
                *(float4*)&a[4] = *(const float4*)&Xs[kk][64 + ti * 4];
                *(float4*)&b[0] = *(const float4*)&Ws[kk][tj * 8];
                *(float4*)&b[4] = *(const float4*)&Ws[kk][tj * 8 + 4];
                #pragma unroll
                for (int u = 0; u < 8; ++u)
                    #pragma unroll
                    for (int v = 0; v < 8; ++v)
                        acc[u][v] += a[u] * b[v];
            }
        }
    }

    float bi[8];
    #pragma unroll
    for (int v = 0; v < 8; ++v) bi[v] = bias[tj * 8 + v];

    if (mode == 0) {
        #pragma unroll
        for (int u = 0; u < 8; ++u) {
            int lr = (u < 4) ? (ti * 4 + u) : (64 + ti * 4 + (u - 4));
            size_t row = rowbase + lr;
            const float* tap = ta + (size_t)tvec[row] * 128 + tj * 8;
            float o[8];
            #pragma unroll
            for (int v = 0; v < 8; ++v)
                o[v] = tanhf(acc[u][v] + bi[v] + tap[v]);
            float* dst = out + row * 128 + tj * 8;
            *(float4*)(dst)     = make_float4(o[0], o[1], o[2], o[3]);
            *(float4*)(dst + 4) = make_float4(o[4], o[5], o[6], o[7]);
        }
    } else {
        // relu + max over each parent's 16 rows (relu >= 0, init 0 safe)
        float m0[8], m1[8];
        #pragma unroll
        for (int v = 0; v < 8; ++v) { m0[v] = 0.f; m1[v] = 0.f; }
        #pragma unroll
        for (int u = 0; u < 4; ++u)
            #pragma unroll
            for (int v = 0; v < 8; ++v) {
                m0[v] = fmaxf(m0[v], fmaxf(acc[u][v]     + bi[v], 0.f));
                m1[v] = fmaxf(m1[v], fmaxf(acc[u + 4][v] + bi[v], 0.f));
            }
        // threads ti = 4q..4q+3 (adjacent lanes) share a parent group
        #pragma unroll
        for (int v = 0; v < 8; ++v) {
            m0[v] = fmaxf(m0[v], __shfl_down_sync(0xffffffffu, m0[v], 2));
            m0[v] = fmaxf(m0[v], __shfl_down_sync(0xffffffffu, m0[v], 1));
            m1[v] = fmaxf(m1[v], __shfl_down_sync(0xffffffffu, m1[v], 2));
            m1[v] = fmaxf(m1[v], __shfl_down_sync(0xffffffffu, m1[v], 1));
        }
        if ((ti & 3) == 0) {
            size_t g0 = (size_t)blockIdx.x * 8 + (ti >> 2);      // rows 0..63
            size_t g1 = g0 + 4;                                  // rows 64..127
            float* d0 = out + g0 * 128 + tj * 8;
            float* d1 = out + g1 * 128 + tj * 8;
            *(float4*)(d0)     = make_float4(m0[0], m0[1], m0[2], m0[3]);
            *(float4*)(d0 + 4) = make_float4(m0[4], m0[5], m0[6], m0[7]);
            *(float4*)(d1)     = make_float4(m1[0], m1[1], m1[2], m1[3]);
            *(float4*)(d1 + 4) = make_float4(m1[4], m1[5], m1[6], m1[7]);
        }
    }
}

// ---------------- launch -----------------------------------------------
extern "C" void kernel_launch(void* const* d_in, const int* in_sizes, int n_in,
                              void* d_out, int out_size) {
    const float* x0   = (const float*)d_in[0];
    const float* x1   = (const float*)d_in[1];
    const float* x2   = (const float*)d_in[2];
    const int*   t0   = (const int*)  d_in[3];
    const int*   t1   = (const int*)  d_in[4];
    const int*   t2   = (const int*)  d_in[5];
    const float* A0   = (const float*)d_in[6];
    const float* A1   = (const float*)d_in[7];
    const float* E0   = (const float*)d_in[8];
    const float* E1   = (const float*)d_in[9];
    const float* W_fe = (const float*)d_in[10];
    const float* b_fe = (const float*)d_in[11];
    const float* W_x  = (const float*)d_in[12];
    const float* W_h  = (const float*)d_in[13];
    const float* W_e  = (const float*)d_in[14];
    const float* W_g  = (const float*)d_in[15];
    const float* b_g  = (const float*)d_in[16];
    const float* b_r  = (const float*)d_in[17];

    float *h2, *M, *pooled, *h1, *Wc, *bias;
    cudaGetSymbolAddress((void**)&h2,     g_h2);
    cudaGetSymbolAddress((void**)&M,      g_M);
    cudaGetSymbolAddress((void**)&pooled, g_pooled);
    cudaGetSymbolAddress((void**)&h1,     g_h1);
    cudaGetSymbolAddress((void**)&Wc,     g_Wc);
    cudaGetSymbolAddress((void**)&bias,   g_bias);

    // fold W_fe/b_fe into per-level weights
    prep_wc<<<3 * 128, 128>>>(W_fe, W_x);
    prep_bias<<<3, 128>>>(b_fe, W_x, b_r);

    // level 2 (leaves): h2 = tanh(x2 @ Wc2 + bias2 + W_x[2][128+t2])
    gemm_fused<<<PB_N2 / 128, 256>>>(
        x2, Wc + 2 * 128 * 128, nullptr, nullptr,
        bias + 2 * 128, W_x + 2 * 132 * 128 + 128 * 128, t2, h2, 0);

    // level 1 GNN: gate+mix, then relu-GEMM + maxpool
    gnn_gate<<<PB_N1, 256>>>(A1, E1, W_e + 8, h2, M);
    gemm_fused<<<(PB_N1 * 16) / 128, 256>>>(
        M, W_g + 1 * 128 * 128, nullptr, nullptr,
        b_g + 128, nullptr, nullptr, pooled, 1);

    // h1 = tanh(x1 @ Wc1 + pooled1 @ W_h1 + bias1 + typerow)
    gemm_fused<<<PB_N1 / 128, 256>>>(
        x1, Wc + 1 * 128 * 128, pooled, W_h + 1 * 128 * 128,
        bias + 128, W_x + 1 * 132 * 128 + 128 * 128, t1, h1, 0);

    // level 0 GNN
    gnn_gate<<<PB_N0, 256>>>(A0, E0, W_e, h1, M);
    gemm_fused<<<(PB_N0 * 16) / 128, 256>>>(
        M, W_g, nullptr, nullptr,
        b_g, nullptr, nullptr, pooled, 1);

    // roots: h0 -> d_out
    gemm_fused<<<PB_N0 / 128, 256>>>(
        x0, Wc, pooled, W_h,
        bias, W_x + 128 * 128, t0, (float*)d_out, 0);
}

// round 3
// speedup vs baseline: 2.3916x; 2.3916x over previous
#include <cuda_runtime.h>
#include <math.h>

// Problem constants
#define PB_N0 2048
#define PB_N1 32768
#define PB_N2 524288
#define PB_C  16
#define PB_D  128
#define PB_H  128
#define PB_ED 8

#define WS_STRIDE 132   // padded stride for 128-wide smem tiles (conflict-free frags)
#define XS_STRIDE 20    // padded stride for 16-wide K chunks
#define GS_STRIDE 20    // padded stride for 16-wide gate rows

// ---------------- scratch (device globals; no runtime allocation) ----------
__device__ float g_pooled[(size_t)PB_N1 * PB_H];  // 16.8 MB (reused at level 0)
__device__ float g_h1[(size_t)PB_N1 * PB_H];      // 16.8 MB
__device__ float g_Wc[3 * PB_D * PB_H];           // W_fe @ W_x[l][:128]
__device__ float g_bias[3 * PB_H];                // b_fe @ W_x[l][:128] + b_r[l]

// ---------------- tf32 helpers ---------------------------------------------
__device__ __forceinline__ unsigned f2tf(float f) {
    unsigned r; asm("cvt.rna.tf32.f32 %0, %1;" : "=r"(r) : "f"(f)); return r;
}
__device__ __forceinline__ void mma8(float4& d, const unsigned a[4],
                                     unsigned b0, unsigned b1) {
    asm volatile(
        "mma.sync.aligned.m16n8k8.row.col.f32.tf32.tf32.f32 "
        "{%0,%1,%2,%3},{%4,%5,%6,%7},{%8,%9},{%0,%1,%2,%3};"
        : "+f"(d.x), "+f"(d.y), "+f"(d.z), "+f"(d.w)
        : "r"(a[0]), "r"(a[1]), "r"(a[2]), "r"(a[3]), "r"(b0), "r"(b1));
}

// ---------------- prep: Wc[l] = W_fe @ W_x[l][0:128,:] ---------------------
__global__ void prep_wc(const float* __restrict__ W_fe,
                        const float* __restrict__ W_x) {
    int l = blockIdx.x >> 7;
    int d = blockIdx.x & 127;
    int h = threadIdx.x;
    const float* wx = W_x + (size_t)l * 132 * 128;
    float acc = 0.f;
    #pragma unroll 8
    for (int k = 0; k < 128; ++k)
        acc += W_fe[d * 128 + k] * wx[k * 128 + h];
    g_Wc[((size_t)l * 128 + d) * 128 + h] = acc;
}

__global__ void prep_bias(const float* __restrict__ b_fe,
                          const float* __restrict__ W_x,
                          const float* __restrict__ b_r) {
    int l = blockIdx.x;
    int h = threadIdx.x;
    const float* wx = W_x + (size_t)l * 132 * 128;
    float acc = b_r[l * 128 + h];
    #pragma unroll 8
    for (int d = 0; d < 128; ++d)
        acc += b_fe[d] * wx[d * 128 + h];
    g_bias[l * 128 + h] = acc;
}

// ============================================================================
// fused_level: per block handles 128 child rows = 8 parents.
//   Phase A (if xin): child_h = tanh(xin @ Wc + bias + typerow) -> smem (tf32)
//           (else)  : child_h loaded from hin -> smem (tf32)
//   Phase B: gates G[p][c][k] = A * sigmoid(E . We)             -> smem (tf32)
//   Phase C: M_p = G_p @ child_h_p (per-parent 16x16 @ 16x128, mma)
//   Phase D: Hc = relu(M @ Wg + bg); maxpool 16 rows -> pooled[parent]
// All GEMMs use tf32 mma.sync m16n8k8, fp32 accumulate.
// ============================================================================
__global__ void __launch_bounds__(256, 2)
fused_level(const float* __restrict__ xin, const int* __restrict__ tvec,
            const float* __restrict__ tapg, const float* __restrict__ Wc,
            const float* __restrict__ biasg,
            const float* __restrict__ hin,
            const float* __restrict__ Ag, const float* __restrict__ Eg,
            const float* __restrict__ Weg,
            const float* __restrict__ Wg, const float* __restrict__ bgg,
            float* __restrict__ pooled)
{
    extern __shared__ unsigned char smraw[];
    unsigned* h2s = (unsigned*)smraw;                                   // [128][132]
    unsigned* Xs  = (unsigned*)(smraw + 128 * WS_STRIDE * 4);           // [128][20]
    unsigned* Wks = (unsigned*)(smraw + (128 * WS_STRIDE + 128 * XS_STRIDE) * 4); // [16][132]
    unsigned* Gs  = (unsigned*)(smraw + (128 * WS_STRIDE + 128 * XS_STRIDE + 16 * WS_STRIDE) * 4); // [8*16][20]
    float* taps   = (float*)(Gs + 8 * 16 * GS_STRIDE);                  // [4][128]
    float* bgs    = taps + 4 * 128;                                     // [128]
    float* biass  = bgs + 128;                                          // [128]
    int*   ts     = (int*)(biass + 128);                                // [128]

    const int t = threadIdx.x;
    const int lane = t & 31, wid = t >> 5;
    const int warpM = wid >> 2, warpN = wid & 3;
    const int g = lane >> 2, tg = lane & 3;
    const size_t rowbase = (size_t)blockIdx.x * 128;

    if (t < 128) bgs[t] = bgg[t];

    float4 acc[4][4];

    if (xin) {
        if (t < 128) { biass[t] = biasg[t]; ts[t] = tvec[rowbase + t]; }
        taps[t] = tapg[t]; taps[t + 256] = tapg[t + 256];

        #pragma unroll
        for (int i = 0; i < 4; ++i)
            #pragma unroll
            for (int j = 0; j < 4; ++j) acc[i][j] = make_float4(0.f, 0.f, 0.f, 0.f);

        for (int kb = 0; kb < 128; kb += 16) {
            #pragma unroll
            for (int u = 0; u < 2; ++u) {               // X chunk 128x16
                int f = t + u * 256; int r = f >> 2, c4 = (f & 3) * 4;
                float4 v = *(const float4*)(xin + (rowbase + r) * 128 + kb + c4);
                unsigned* d = Xs + r * XS_STRIDE + c4;
                d[0] = f2tf(v.x); d[1] = f2tf(v.y); d[2] = f2tf(v.z); d[3] = f2tf(v.w);
            }
            #pragma unroll
            for (int u = 0; u < 2; ++u) {               // W chunk 16x128
                int f = t + u * 256; int r = f >> 5, c4 = (f & 31) * 4;
                float4 v = *(const float4*)(Wc + (size_t)(kb + r) * 128 + c4);
                unsigned* d = Wks + r * WS_STRIDE + c4;
                d[0] = f2tf(v.x); d[1] = f2tf(v.y); d[2] = f2tf(v.z); d[3] = f2tf(v.w);
            }
            __syncthreads();
            #pragma unroll
            for (int ks = 0; ks < 2; ++ks) {
                int k0 = ks * 8;
                unsigned a[4][4], b[4][2];
                #pragma unroll
                for (int i = 0; i < 4; ++i) {
                    int rb = warpM * 64 + i * 16;
                    a[i][0] = Xs[(rb + g) * XS_STRIDE + k0 + tg];
                    a[i][1] = Xs[(rb + g + 8) * XS_STRIDE + k0 + tg];
                    a[i][2] = Xs[(rb + g) * XS_STRIDE + k0 + tg + 4];
                    a[i][3] = Xs[(rb + g + 8) * XS_STRIDE + k0 + tg + 4];
                }
                #pragma unroll
                for (int j = 0; j < 4; ++j) {
                    int col = warpN * 32 + j * 8 + g;
                    b[j][0] = Wks[(k0 + tg) * WS_STRIDE + col];
                    b[j][1] = Wks[(k0 + tg + 4) * WS_STRIDE + col];
                }
                #pragma unroll
                for (int i = 0; i < 4; ++i)
                    #pragma unroll
                    for (int j = 0; j < 4; ++j) mma8(acc[i][j], a[i], b[j][0], b[j][1]);
            }
            __syncthreads();
        }
        // epilogue: tanh -> h2s (tf32 bits)
        #pragma unroll
        for (int i = 0; i < 4; ++i) {
            int r0 = warpM * 64 + i * 16 + g, r1 = r0 + 8;
            const float* tap0 = taps + ts[r0] * 128;
            const float* tap1 = taps + ts[r1] * 128;
            #pragma unroll
            for (int j = 0; j < 4; ++j) {
                int c0 = warpN * 32 + j * 8 + tg * 2;
                h2s[r0 * WS_STRIDE + c0]     = f2tf(tanhf(acc[i][j].x + biass[c0]     + tap0[c0]));
                h2s[r0 * WS_STRIDE + c0 + 1] = f2tf(tanhf(acc[i][j].y + biass[c0 + 1] + tap0[c0 + 1]));
                h2s[r1 * WS_STRIDE + c0]     = f2tf(tanhf(acc[i][j].z + biass[c0]     + tap1[c0]));
                h2s[r1 * WS_STRIDE + c0 + 1] = f2tf(tanhf(acc[i][j].w + biass[c0 + 1] + tap1[c0 + 1]));
            }
        }
    } else {
        // load child hidden tile from global
        #pragma unroll
        for (int u = 0; u < 16; ++u) {
            int f = t + u * 256; int r = f >> 5, c4 = (f & 31) * 4;
            float4 v = *(const float4*)(hin + (rowbase + r) * 128 + c4);
            unsigned* d = h2s + r * WS_STRIDE + c4;
            d[0] = f2tf(v.x); d[1] = f2tf(v.y); d[2] = f2tf(v.z); d[3] = f2tf(v.w);
        }
    }

    // Phase B: gates (writes Gs only; no smem reads)
    {
        const size_t edgebase = (size_t)blockIdx.x * 2048;   // 8 parents * 256 edges
        float we0 = Weg[0], we1 = Weg[1], we2 = Weg[2], we3 = Weg[3];
        float we4 = Weg[4], we5 = Weg[5], we6 = Weg[6], we7 = Weg[7];
        #pragma unroll
        for (int u = 0; u < 8; ++u) {
            int idx = t + u * 256;                           // p*256 + c*16 + k
            const float* e = Eg + (edgebase + idx) * 8;
            float4 e0 = *(const float4*)(e);
            float4 e1 = *(const float4*)(e + 4);
            float s = e0.x * we0 + e0.y * we1 + e0.z * we2 + e0.w * we3
                    + e1.x * we4 + e1.y * we5 + e1.z * we6 + e1.w * we7;
            float gte = Ag[edgebase + idx] / (1.f + __expf(-s));
            int p = idx >> 8, c = (idx >> 4) & 15, k = idx & 15;
            Gs[(p * 16 + c) * GS_STRIDE + k] = f2tf(gte);
        }
    }
    __syncthreads();

    // Phase C: per-parent mix M_p = G_p @ child_h_p  (warp wid = parent)
    {
        float4 macc[16];
        #pragma unroll
        for (int j = 0; j < 16; ++j) macc[j] = make_float4(0.f, 0.f, 0.f, 0.f);
        int p = wid;
        #pragma unroll
        for (int ks = 0; ks < 2; ++ks) {
            int k0 = ks * 8;
            unsigned a[4];
            a[0] = Gs[(p * 16 + g) * GS_STRIDE + k0 + tg];
            a[1] = Gs[(p * 16 + g + 8) * GS_STRIDE + k0 + tg];
            a[2] = Gs[(p * 16 + g) * GS_STRIDE + k0 + tg + 4];
            a[3] = Gs[(p * 16 + g + 8) * GS_STRIDE + k0 + tg + 4];
            #pragma unroll
            for (int j = 0; j < 16; ++j) {
                unsigned b0 = h2s[(p * 16 + k0 + tg) * WS_STRIDE + j * 8 + g];
                unsigned b1 = h2s[(p * 16 + k0 + tg + 4) * WS_STRIDE + j * 8 + g];
                mma8(macc[j], a, b0, b1);
            }
        }
        __syncwarp();
        // overwrite own parent's rows with M (only this warp reads/writes them)
        #pragma unroll
        for (int j = 0; j < 16; ++j) {
            int c0 = j * 8 + tg * 2;
            h2s[(p * 16 + g) * WS_STRIDE + c0]         = f2tf(macc[j].x);
            h2s[(p * 16 + g) * WS_STRIDE + c0 + 1]     = f2tf(macc[j].y);
            h2s[(p * 16 + g + 8) * WS_STRIDE + c0]     = f2tf(macc[j].z);
            h2s[(p * 16 + g + 8) * WS_STRIDE + c0 + 1] = f2tf(macc[j].w);
        }
    }
    __syncthreads();

    // Phase D: Hc = relu(M @ Wg + bg); maxpool over each parent's 16 rows
    #pragma unroll
    for (int i = 0; i < 4; ++i)
        #pragma unroll
        for (int j = 0; j < 4; ++j) acc[i][j] = make_float4(0.f, 0.f, 0.f, 0.f);

    for (int kb = 0; kb < 128; kb += 16) {
        #pragma unroll
        for (int u = 0; u < 2; ++u) {
            int f = t + u * 256; int r = f >> 5, c4 = (f & 31) * 4;
            float4 v = *(const float4*)(Wg + (size_t)(kb + r) * 128 + c4);
            unsigned* d = Wks + r * WS_STRIDE + c4;
            d[0] = f2tf(v.x); d[1] = f2tf(v.y); d[2] = f2tf(v.z); d[3] = f2tf(v.w);
        }
        __syncthreads();
        #pragma unroll
        for (int ks = 0; ks < 2; ++ks) {
            int k0 = kb + ks * 8;
            unsigned a[4][4], b[4][2];
            #pragma unroll
            for (int i = 0; i < 4; ++i) {
                int rb = warpM * 64 + i * 16;
                a[i][0] = h2s[(rb + g) * WS_STRIDE + k0 + tg];
                a[i][1] = h2s[(rb + g + 8) * WS_STRIDE + k0 + tg];
                a[i][2] = h2s[(rb + g) * WS_STRIDE + k0 + tg + 4];
                a[i][3] = h2s[(rb + g + 8) * WS_STRIDE + k0 + tg + 4];
            }
            #pragma unroll
            for (int j = 0; j < 4; ++j) {
                int col = warpN * 32 + j * 8 + g;
                b[j][0] = Wks[(ks * 8 + tg) * WS_STRIDE + col];
                b[j][1] = Wks[(ks * 8 + tg + 4) * WS_STRIDE + col];
            }
            #pragma unroll
            for (int i = 0; i < 4; ++i)
                #pragma unroll
                for (int j = 0; j < 4; ++j) mma8(acc[i][j], a[i], b[j][0], b[j][1]);
        }
        __syncthreads();
    }

    // relu + 16-row maxpool (m-tile i == parent warpM*4+i exactly)
    #pragma unroll
    for (int i = 0; i < 4; ++i) {
        size_t parent = (size_t)blockIdx.x * 8 + warpM * 4 + i;
        #pragma unroll
        for (int j = 0; j < 4; ++j) {
            int c0 = warpN * 32 + j * 8 + tg * 2;
            float b0 = bgs[c0], b1 = bgs[c0 + 1];
            float v0 = fmaxf(fmaxf(acc[i][j].x + b0, acc[i][j].z + b0), 0.f);
            float v1 = fmaxf(fmaxf(acc[i][j].y + b1, acc[i][j].w + b1), 0.f);
            #pragma unroll
            for (int off = 16; off >= 4; off >>= 1) {
                v0 = fmaxf(v0, __shfl_xor_sync(0xffffffffu, v0, off));
                v1 = fmaxf(v1, __shfl_xor_sync(0xffffffffu, v1, off));
            }
            if (lane < 4)
                *(float2*)(pooled + parent * 128 + c0) = make_float2(v0, v1);
        }
    }
}

// ============================================================================
// gemm_tanh: out = tanh(A0 @ W0 + A1 @ W1 + bias + typerow[t]) , tf32 mma
// ============================================================================
__global__ void __launch_bounds__(256, 2)
gemm_tanh(const float* __restrict__ A0g, const float* __restrict__ W0,
          const float* __restrict__ A1g, const float* __restrict__ W1,
          const float* __restrict__ biasg, const float* __restrict__ tapg,
          const int* __restrict__ tvec, float* __restrict__ out)
{
    __shared__ unsigned Xs[128][XS_STRIDE];
    __shared__ unsigned Wks[16][WS_STRIDE];
    __shared__ float taps[4][128];
    __shared__ float biass[128];
    __shared__ int ts[128];

    const int t = threadIdx.x;
    const int lane = t & 31, wid = t >> 5;
    const int warpM = wid >> 2, warpN = wid & 3;
    const int g = lane >> 2, tg = lane & 3;
    const size_t rowbase = (size_t)blockIdx.x * 128;

    if (t < 128) { biass[t] = biasg[t]; ts[t] = tvec[rowbase + t]; }
    ((float*)taps)[t] = tapg[t]; ((float*)taps)[t + 256] = tapg[t + 256];

    float4 acc[4][4];
    #pragma unroll
    for (int i = 0; i < 4; ++i)
        #pragma unroll
        for (int j = 0; j < 4; ++j) acc[i][j] = make_float4(0.f, 0.f, 0.f, 0.f);

    for (int seg = 0; seg < 2; ++seg) {
        const float* A = seg ? A1g : A0g;
        const float* W = seg ? W1 : W0;
        for (int kb = 0; kb < 128; kb += 16) {
            #pragma unroll
            for (int u = 0; u < 2; ++u) {
                int f = t + u * 256; int r = f >> 2, c4 = (f & 3) * 4;
                float4 v = *(const float4*)(A + (rowbase + r) * 128 + kb + c4);
                unsigned* d = &Xs[r][c4];
                d[0] = f2tf(v.x); d[1] = f2tf(v.y); d[2] = f2tf(v.z); d[3] = f2tf(v.w);
            }
            #pragma unroll
            for (int u = 0; u < 2; ++u) {
                int f = t + u * 256; int r = f >> 5, c4 = (f & 31) * 4;
                float4 v = *(const float4*)(W + (size_t)(kb + r) * 128 + c4);
                unsigned* d = &Wks[r][c4];
                d[0] = f2tf(v.x); d[1] = f2tf(v.y); d[2] = f2tf(v.z); d[3] = f2tf(v.w);
            }
            __syncthreads();
            #pragma unroll
            for (int ks = 0; ks < 2; ++ks) {
                int k0 = ks * 8;
                unsigned a[4][4], b[4][2];
                #pragma unroll
                for (int i = 0; i < 4; ++i) {
                    int rb = warpM * 64 + i * 16;
                    a[i][0] = Xs[rb + g][k0 + tg];
                    a[i][1] = Xs[rb + g + 8][k0 + tg];
                    a[i][2] = Xs[rb + g][k0 + tg + 4];
                    a[i][3] = Xs[rb + g + 8][k0 + tg + 4];
                }
                #pragma unroll
                for (int j = 0; j < 4; ++j) {
                    int col = warpN * 32 + j * 8 + g;
                    b[j][0] = Wks[k0 + tg][col];
                    b[j][1] = Wks[k0 + tg + 4][col];
                }
                #pragma unroll
                for (int i = 0; i < 4; ++i)
                    #pragma unroll
                    for (int j = 0; j < 4; ++j) mma8(acc[i][j], a[i], b[j][0], b[j][1]);
            }
            __syncthreads();
        }
    }

    #pragma unroll
    for (int i = 0; i < 4; ++i) {
        int r0 = warpM * 64 + i * 16 + g, r1 = r0 + 8;
        const float* tap0 = taps[ts[r0]];
        const float* tap1 = taps[ts[r1]];
        #pragma unroll
        for (int j = 0; j < 4; ++j) {
            int c0 = warpN * 32 + j * 8 + tg * 2;
            float o0 = tanhf(acc[i][j].x + biass[c0]     + tap0[c0]);
            float o1 = tanhf(acc[i][j].y + biass[c0 + 1] + tap0[c0 + 1]);
            float o2 = tanhf(acc[i][j].z + biass[c0]     + tap1[c0]);
            float o3 = tanhf(acc[i][j].w + biass[c0 + 1] + tap1[c0 + 1]);
            *(float2*)(out + (rowbase + r0) * 128 + c0) = make_float2(o0, o1);
            *(float2*)(out + (rowbase + r1) * 128 + c0) = make_float2(o2, o3);
        }
    }
}

// ---------------- launch -----------------------------------------------
extern "C" void kernel_launch(void* const* d_in, const int* in_sizes, int n_in,
                              void* d_out, int out_size) {
    const float* x0   = (const float*)d_in[0];
    const float* x1   = (const float*)d_in[1];
    const float* x2   = (const float*)d_in[2];
    const int*   t0   = (const int*)  d_in[3];
    const int*   t1   = (const int*)  d_in[4];
    const int*   t2   = (const int*)  d_in[5];
    const float* A0   = (const float*)d_in[6];
    const float* A1   = (const float*)d_in[7];
    const float* E0   = (const float*)d_in[8];
    const float* E1   = (const float*)d_in[9];
    const float* W_fe = (const float*)d_in[10];
    const float* b_fe = (const float*)d_in[11];
    const float* W_x  = (const float*)d_in[12];
    const float* W_h  = (const float*)d_in[13];
    const float* W_e  = (const float*)d_in[14];
    const float* W_g  = (const float*)d_in[15];
    const float* b_g  = (const float*)d_in[16];
    const float* b_r  = (const float*)d_in[17];

    float *pooled, *h1, *Wc, *bias;
    cudaGetSymbolAddress((void**)&pooled, g_pooled);
    cudaGetSymbolAddress((void**)&h1,     g_h1);
    cudaGetSymbolAddress((void**)&Wc,     g_Wc);
    cudaGetSymbolAddress((void**)&bias,   g_bias);

    const int SMEMSZ = (128 * WS_STRIDE + 128 * XS_STRIDE + 16 * WS_STRIDE +
                        8 * 16 * GS_STRIDE) * 4 + (4 * 128 + 128 + 128) * 4 + 128 * 4;
    cudaFuncSetAttribute(fused_level, cudaFuncAttributeMaxDynamicSharedMemorySize, SMEMSZ);

    // fold W_fe/b_fe into per-level weights
    prep_wc<<<3 * 128, 128>>>(W_fe, W_x);
    prep_bias<<<3, 128>>>(b_fe, W_x, b_r);

    // level 2 + level 1 GNN fused: x2 -> h2 (smem) -> gate/mix -> relu GEMM -> pooled1
    fused_level<<<PB_N2 / 128, 256, SMEMSZ>>>(
        x2, t2, W_x + 2 * 132 * 128 + 128 * 128, Wc + 2 * 128 * 128, bias + 2 * 128,
        nullptr, A1, E1, W_e + 8, W_g + 128 * 128, b_g + 128, pooled);

    // h1 = tanh(x1 @ Wc1 + pooled1 @ W_h1 + bias1 + typerow)
    gemm_tanh<<<PB_N1 / 128, 256>>>(
        x1, Wc + 128 * 128, pooled, W_h + 128 * 128,
        bias + 128, W_x + 132 * 128 + 128 * 128, t1, h1);

    // level 0 GNN fused (child hidden loaded from h1)
    fused_level<<<PB_N1 / 128, 256, SMEMSZ>>>(
        nullptr, nullptr, nullptr, nullptr, nullptr,
        h1, A0, E0, W_e, W_g, b_g, pooled);

    // roots: h0 -> d_out
    gemm_tanh<<<PB_N0 / 128, 256>>>(
        x0, Wc, pooled, W_h,
        bias, W_x + 128 * 128, t0, (float*)d_out);
}

// round 4
// speedup vs baseline: 2.7475x; 1.1488x over previous
#include <cuda_runtime.h>
#include <math.h>

// Problem constants
#define PB_N0 2048
#define PB_N1 32768
#define PB_N2 524288
#define PB_C  16
#define PB_D  128
#define PB_H  128
#define PB_ED 8

#define WS_STRIDE 132   // padded stride for 128-wide smem tiles
#define XS_STRIDE 20    // padded stride for 16-wide K chunks (conflict-free)

// ---------------- scratch (device globals; no runtime allocation) ----------
__device__ float g_pooled[(size_t)PB_N1 * PB_H];  // 16.8 MB (reused at level 0)
__device__ float g_h1[(size_t)PB_N1 * PB_H];      // 16.8 MB
__device__ float g_Wc[3 * PB_D * PB_H];           // W_fe @ W_x[l][:128]
__device__ float g_bias[3 * PB_H];                // b_fe @ W_x[l][:128] + b_r[l]

// ---------------- tf32 helpers ---------------------------------------------
__device__ __forceinline__ unsigned f2tf(float f) {
    unsigned r; asm("cvt.rna.tf32.f32 %0, %1;" : "=r"(r) : "f"(f)); return r;
}
__device__ __forceinline__ void mma8(float4& d, const unsigned a[4],
                                     unsigned b0, unsigned b1) {
    asm volatile(
        "mma.sync.aligned.m16n8k8.row.col.f32.tf32.tf32.f32 "
        "{%0,%1,%2,%3},{%4,%5,%6,%7},{%8,%9},{%0,%1,%2,%3};"
        : "+f"(d.x), "+f"(d.y), "+f"(d.z), "+f"(d.w)
        : "r"(a[0]), "r"(a[1]), "r"(a[2]), "r"(a[3]), "r"(b0), "r"(b1));
}

// store a prefetched X chunk (regs -> smem, tf32)
__device__ __forceinline__ void storeX(unsigned* Xb, int t,
                                       const float4& xa, const float4& xb) {
    int f = t, r = f >> 2, c4 = (f & 3) * 4;
    unsigned* d = Xb + r * XS_STRIDE + c4;
    d[0] = f2tf(xa.x); d[1] = f2tf(xa.y); d[2] = f2tf(xa.z); d[3] = f2tf(xa.w);
    f = t + 256; r = f >> 2; c4 = (f & 3) * 4;
    d = Xb + r * XS_STRIDE + c4;
    d[0] = f2tf(xb.x); d[1] = f2tf(xb.y); d[2] = f2tf(xb.z); d[3] = f2tf(xb.w);
}
__device__ __forceinline__ void storeW(unsigned* Wb, int t,
                                       const float4& wa, const float4& wb) {
    int f = t, r = f >> 5, c4 = (f & 31) * 4;
    unsigned* d = Wb + r * WS_STRIDE + c4;
    d[0] = f2tf(wa.x); d[1] = f2tf(wa.y); d[2] = f2tf(wa.z); d[3] = f2tf(wa.w);
    f = t + 256; r = f >> 5; c4 = (f & 31) * 4;
    d = Wb + r * WS_STRIDE + c4;
    d[0] = f2tf(wb.x); d[1] = f2tf(wb.y); d[2] = f2tf(wb.z); d[3] = f2tf(wb.w);
}
__device__ __forceinline__ void loadX(const float* A, size_t rowbase, int kb,
                                      int t, float4& xa, float4& xb) {
    int f = t, r = f >> 2, c4 = (f & 3) * 4;
    xa = *(const float4*)(A + (rowbase + r) * 128 + kb + c4);
    f = t + 256; r = f >> 2; c4 = (f & 3) * 4;
    xb = *(const float4*)(A + (rowbase + r) * 128 + kb + c4);
}
__device__ __forceinline__ void loadW(const float* W, int kb,
                                      int t, float4& wa, float4& wb) {
    int f = t, r = f >> 5, c4 = (f & 31) * 4;
    wa = *(const float4*)(W + (size_t)(kb + r) * 128 + c4);
    f = t + 256; r = f >> 5; c4 = (f & 31) * 4;
    wb = *(const float4*)(W + (size_t)(kb + r) * 128 + c4);
}

// one 16-K-deep mma step on a 128x128 tile (per-warp 64x32 sub-tile)
__device__ __forceinline__ void mma_chunk(float4 acc[4][4],
                                          const unsigned* Xb, int xstride,
                                          const unsigned* Wb,
                                          int warpM, int warpN, int g, int tg) {
    #pragma unroll
    for (int ks = 0; ks < 2; ++ks) {
        int k0 = ks * 8;
        unsigned a[4][4], b[4][2];
        #pragma unroll
        for (int i = 0; i < 4; ++i) {
            int rb = warpM * 64 + i * 16;
            a[i][0] = Xb[(rb + g) * xstride + k0 + tg];
            a[i][1] = Xb[(rb + g + 8) * xstride + k0 + tg];
            a[i][2] = Xb[(rb + g) * xstride + k0 + tg + 4];
            a[i][3] = Xb[(rb + g + 8) * xstride + k0 + tg + 4];
        }
        #pragma unroll
        for (int j = 0; j < 4; ++j) {
            int col = warpN * 32 + j * 8 + g;
            b[j][0] = Wb[(k0 + tg) * WS_STRIDE + col];
            b[j][1] = Wb[(k0 + tg + 4) * WS_STRIDE + col];
        }
        #pragma unroll
        for (int i = 0; i < 4; ++i)
            #pragma unroll
            for (int j = 0; j < 4; ++j) mma8(acc[i][j], a[i], b[j][0], b[j][1]);
    }
}

// ---------------- prep: Wc[l] = W_fe @ W_x[l][0:128,:] ---------------------
__global__ void prep_wc(const float* __restrict__ W_fe,
                        const float* __restrict__ W_x) {
    int l = blockIdx.x >> 7;
    int d = blockIdx.x & 127;
    int h = threadIdx.x;
    const float* wx = W_x + (size_t)l * 132 * 128;
    float acc = 0.f;
    #pragma unroll 8
    for (int k = 0; k < 128; ++k)
        acc += W_fe[d * 128 + k] * wx[k * 128 + h];
    g_Wc[((size_t)l * 128 + d) * 128 + h] = acc;
}

__global__ void prep_bias(const float* __restrict__ b_fe,
                          const float* __restrict__ W_x,
                          const float* __restrict__ b_r) {
    int l = blockIdx.x;
    int h = threadIdx.x;
    const float* wx = W_x + (size_t)l * 132 * 128;
    float acc = b_r[l * 128 + h];
    #pragma unroll 8
    for (int d = 0; d < 128; ++d)
        acc += b_fe[d] * wx[d * 128 + h];
    g_bias[l * 128 + h] = acc;
}

// ============================================================================
// fused_level: per block 128 child rows = 8 parents (warp w <-> parent w).
//   A: child_h = tanh(xin @ Wc + bias + typerow) -> smem tf32  (or load hin)
//   gates: each lane computes its 8 mma-A-fragment gate values in registers
//   C: M_p = G_p @ child_h_p per warp (writes back into h2s)
//   D: Hc = relu(M @ Wg + bg); 16-row maxpool -> pooled
// Single-sync double-buffered K pipeline on A and D.
// ============================================================================
__global__ void __launch_bounds__(256, 2)
fused_level(const float* __restrict__ xin, const int* __restrict__ tvec,
            const float* __restrict__ tapg, const float* __restrict__ Wc,
            const float* __restrict__ biasg,
            const float* __restrict__ hin,
            const float* __restrict__ Ag, const float* __restrict__ Eg,
            const float* __restrict__ Weg,
            const float* __restrict__ Wg, const float* __restrict__ bgg,
            float* __restrict__ pooled)
{
    extern __shared__ unsigned char smraw[];
    unsigned* h2s = (unsigned*)smraw;                       // [128][132]
    unsigned* Xs  = h2s + 128 * WS_STRIDE;                  // [2][128][20]
    unsigned* Wks = Xs + 2 * 128 * XS_STRIDE;               // [2][16][132]
    float* taps   = (float*)(Wks + 2 * 16 * WS_STRIDE);     // [4][128]
    float* bgs    = taps + 4 * 128;                         // [128]
    float* biass  = bgs + 128;                              // [128]
    int*   ts     = (int*)(biass + 128);                    // [128]

    const int t = threadIdx.x;
    const int lane = t & 31, wid = t >> 5;
    const int warpM = wid >> 2, warpN = wid & 3;
    const int g = lane >> 2, tg = lane & 3;
    const size_t rowbase = (size_t)blockIdx.x * 128;

    if (t < 128) bgs[t] = bgg[t];

    float4 acc[4][4];
    float gg[2][2][2];   // [c8][k8][k4] gate values for this lane's parent

    if (xin) {
        if (t < 128) { biass[t] = biasg[t]; ts[t] = tvec[rowbase + t]; }
        taps[t] = tapg[t]; taps[t + 256] = tapg[t + 256];

        #pragma unroll
        for (int i = 0; i < 4; ++i)
            #pragma unroll
            for (int j = 0; j < 4; ++j) acc[i][j] = make_float4(0.f, 0.f, 0.f, 0.f);

        float4 xa, xb, wa, wb;
        loadX(xin, rowbase, 0, t, xa, xb);
        loadW(Wc, 0, t, wa, wb);
        #pragma unroll
        for (int it = 0; it < 8; ++it) {
            unsigned* Xb = Xs + (it & 1) * 128 * XS_STRIDE;
            unsigned* Wb = Wks + (it & 1) * 16 * WS_STRIDE;
            storeX(Xb, t, xa, xb);
            storeW(Wb, t, wa, wb);
            __syncthreads();
            if (it < 7) {
                loadX(xin, rowbase, (it + 1) * 16, t, xa, xb);
                loadW(Wc, (it + 1) * 16, t, wa, wb);
            }
            mma_chunk(acc, Xb, XS_STRIDE, Wb, warpM, warpN, g, tg);
        }

        // gates (register-resident, loads overlap epilogue latency below)
        {
            const size_t ebase = (size_t)blockIdx.x * 2048 + wid * 256;
            float we0 = Weg[0], we1 = Weg[1], we2 = Weg[2], we3 = Weg[3];
            float we4 = Weg[4], we5 = Weg[5], we6 = Weg[6], we7 = Weg[7];
            #pragma unroll
            for (int c8 = 0; c8 < 2; ++c8)
                #pragma unroll
                for (int k8 = 0; k8 < 2; ++k8)
                    #pragma unroll
                    for (int k4 = 0; k4 < 2; ++k4) {
                        int c = g + 8 * c8, k = tg + 4 * k4 + 8 * k8;
                        const float* e = Eg + (ebase + c * 16 + k) * 8;
                        float4 e0 = *(const float4*)(e);
                        float4 e1 = *(const float4*)(e + 4);
                        float s = e0.x * we0 + e0.y * we1 + e0.z * we2 + e0.w * we3
                                + e1.x * we4 + e1.y * we5 + e1.z * we6 + e1.w * we7;
                        gg[c8][k8][k4] = Ag[ebase + c * 16 + k] / (1.f + __expf(-s));
                    }
        }

        // epilogue: tanh -> h2s (tf32 bits)
        #pragma unroll
        for (int i = 0; i < 4; ++i) {
            int r0 = warpM * 64 + i * 16 + g, r1 = r0 + 8;
            const float* tap0 = taps + ts[r0] * 128;
            const float* tap1 = taps + ts[r1] * 128;
            #pragma unroll
            for (int j = 0; j < 4; ++j) {
                int c0 = warpN * 32 + j * 8 + tg * 2;
                h2s[r0 * WS_STRIDE + c0]     = f2tf(tanhf(acc[i][j].x + biass[c0]     + tap0[c0]));
                h2s[r0 * WS_STRIDE + c0 + 1] = f2tf(tanhf(acc[i][j].y + biass[c0 + 1] + tap0[c0 + 1]));
                h2s[r1 * WS_STRIDE + c0]     = f2tf(tanhf(acc[i][j].z + biass[c0]     + tap1[c0]));
                h2s[r1 * WS_STRIDE + c0 + 1] = f2tf(tanhf(acc[i][j].w + biass[c0 + 1] + tap1[c0 + 1]));
            }
        }
    } else {
        // load child hidden tile from global
        #pragma unroll
        for (int u = 0; u < 16; ++u) {
            int f = t + u * 256; int r = f >> 5, c4 = (f & 31) * 4;
            float4 v = *(const float4*)(hin + (rowbase + r) * 128 + c4);
            unsigned* d = h2s + r * WS_STRIDE + c4;
            d[0] = f2tf(v.x); d[1] = f2tf(v.y); d[2] = f2tf(v.z); d[3] = f2tf(v.w);
        }
        {
            const size_t ebase = (size_t)blockIdx.x * 2048 + wid * 256;
            float we0 = Weg[0], we1 = Weg[1], we2 = Weg[2], we3 = Weg[3];
            float we4 = Weg[4], we5 = Weg[5], we6 = Weg[6], we7 = Weg[7];
            #pragma unroll
            for (int c8 = 0; c8 < 2; ++c8)
                #pragma unroll
                for (int k8 = 0; k8 < 2; ++k8)
                    #pragma unroll
                    for (int k4 = 0; k4 < 2; ++k4) {
                        int c = g + 8 * c8, k = tg + 4 * k4 + 8 * k8;
                        const float* e = Eg + (ebase + c * 16 + k) * 8;
                        float4 e0 = *(const float4*)(e);
                        float4 e1 = *(const float4*)(e + 4);
                        float s = e0.x * we0 + e0.y * we1 + e0.z * we2 + e0.w * we3
                                + e1.x * we4 + e1.y * we5 + e1.z * we6 + e1.w * we7;
                        gg[c8][k8][k4] = Ag[ebase + c * 16 + k] / (1.f + __expf(-s));
                    }
        }
    }
    __syncthreads();   // h2s complete, all warps may read any parent rows

    // Phase C: per-parent mix M_p = G_p @ child_h_p  (warp wid = parent)
    {
        float4 macc[16];
        #pragma unroll
        for (int j = 0; j < 16; ++j) macc[j] = make_float4(0.f, 0.f, 0.f, 0.f);
        int p = wid;
        #pragma unroll
        for (int ks = 0; ks < 2; ++ks) {
            unsigned a[4];
            a[0] = f2tf(gg[0][ks][0]);
            a[1] = f2tf(gg[1][ks][0]);
            a[2] = f2tf(gg[0][ks][1]);
            a[3] = f2tf(gg[1][ks][1]);
            #pragma unroll
            for (int j = 0; j < 16; ++j) {
                unsigned b0 = h2s[(p * 16 + ks * 8 + tg) * WS_STRIDE + j * 8 + g];
                unsigned b1 = h2s[(p * 16 + ks * 8 + tg + 4) * WS_STRIDE + j * 8 + g];
                mma8(macc[j], a, b0, b1);
            }
        }
        __syncwarp();
        #pragma unroll
        for (int j = 0; j < 16; ++j) {
            int c0 = j * 8 + tg * 2;
            h2s[(p * 16 + g) * WS_STRIDE + c0]         = f2tf(macc[j].x);
            h2s[(p * 16 + g) * WS_STRIDE + c0 + 1]     = f2tf(macc[j].y);
            h2s[(p * 16 + g + 8) * WS_STRIDE + c0]     = f2tf(macc[j].z);
            h2s[(p * 16 + g + 8) * WS_STRIDE + c0 + 1] = f2tf(macc[j].w);
        }
    }
    __syncthreads();

    // Phase D: Hc = relu(M @ Wg + bg); maxpool over each parent's 16 rows
    #pragma unroll
    for (int i = 0; i < 4; ++i)
        #pragma unroll
        for (int j = 0; j < 4; ++j) acc[i][j] = make_float4(0.f, 0.f, 0.f, 0.f);

    {
        float4 wa, wb;
        loadW(Wg, 0, t, wa, wb);
        #pragma unroll
        for (int it = 0; it < 8; ++it) {
            unsigned* Wb = Wks + (it & 1) * 16 * WS_STRIDE;
            storeW(Wb, t, wa, wb);
            __syncthreads();
            if (it < 7) loadW(Wg, (it + 1) * 16, t, wa, wb);
            #pragma unroll
            for (int ks = 0; ks < 2; ++ks) {
                int k0 = it * 16 + ks * 8;
                unsigned a[4][4], b[4][2];
                #pragma unroll
                for (int i = 0; i < 4; ++i) {
                    int rb = warpM * 64 + i * 16;
                    a[i][0] = h2s[(rb + g) * WS_STRIDE + k0 + tg];
                    a[i][1] = h2s[(rb + g + 8) * WS_STRIDE + k0 + tg];
                    a[i][2] = h2s[(rb + g) * WS_STRIDE + k0 + tg + 4];
                    a[i][3] = h2s[(rb + g + 8) * WS_STRIDE + k0 + tg + 4];
                }
                #pragma unroll
                for (int j = 0; j < 4; ++j) {
                    int col = warpN * 32 + j * 8 + g;
                    b[j][0] = Wb[(ks * 8 + tg) * WS_STRIDE + col];
                    b[j][1] = Wb[(ks * 8 + tg + 4) * WS_STRIDE + col];
                }
                #pragma unroll
                for (int i = 0; i < 4; ++i)
                    #pragma unroll
                    for (int j = 0; j < 4; ++j) mma8(acc[i][j], a[i], b[j][0], b[j][1]);
            }
        }
    }

    // relu + 16-row maxpool (m-tile i == parent warpM*4+i exactly)
    #pragma unroll
    for (int i = 0; i < 4; ++i) {
        size_t parent = (size_t)blockIdx.x * 8 + warpM * 4 + i;
        #pragma unroll
        for (int j = 0; j < 4; ++j) {
            int c0 = warpN * 32 + j * 8 + tg * 2;
            float b0 = bgs[c0], b1 = bgs[c0 + 1];
            float v0 = fmaxf(fmaxf(acc[i][j].x + b0, acc[i][j].z + b0), 0.f);
            float v1 = fmaxf(fmaxf(acc[i][j].y + b1, acc[i][j].w + b1), 0.f);
            #pragma unroll
            for (int off = 16; off >= 4; off >>= 1) {
                v0 = fmaxf(v0, __shfl_xor_sync(0xffffffffu, v0, off));
                v1 = fmaxf(v1, __shfl_xor_sync(0xffffffffu, v1, off));
            }
            if (lane < 4)
                *(float2*)(pooled + parent * 128 + c0) = make_float2(v0, v1);
        }
    }
}

// ============================================================================
// gemm_tanh: out = tanh(A0 @ W0 + A1 @ W1 + bias + typerow[t]) , tf32 mma
// Single-sync double-buffered 16-chunk pipeline (2 segments x 8 chunks).
// ============================================================================
__global__ void __launch_bounds__(256, 2)
gemm_tanh(const float* __restrict__ A0g, const float* __restrict__ W0,
          const float* __restrict__ A1g, const float* __restrict__ W1,
          const float* __restrict__ biasg, const float* __restrict__ tapg,
          const int* __restrict__ tvec, float* __restrict__ out)
{
    __shared__ unsigned Xs[2][128 * XS_STRIDE];
    __shared__ unsigned Wks[2][16 * WS_STRIDE];
    __shared__ float taps[4][128];
    __shared__ float biass[128];
    __shared__ int ts[128];

    const int t = threadIdx.x;
    const int lane = t & 31, wid = t >> 5;
    const int warpM = wid >> 2, warpN = wid & 3;
    const int g = lane >> 2, tg = lane & 3;
    const size_t rowbase = (size_t)blockIdx.x * 128;

    if (t < 128) { biass[t] = biasg[t]; ts[t] = tvec[rowbase + t]; }
    ((float*)taps)[t] = tapg[t]; ((float*)taps)[t + 256] = tapg[t + 256];

    const float* Aseg[2] = {A0g, A1g};
    const float* Wseg[2] = {W0, W1};

    float4 acc[4][4];
    #pragma unroll
    for (int i = 0; i < 4; ++i)
        #pragma unroll
        for (int j = 0; j < 4; ++j) acc[i][j] = make_float4(0.f, 0.f, 0.f, 0.f);

    float4 xa, xb, wa, wb;
    loadX(A0g, rowbase, 0, t, xa, xb);
    loadW(W0, 0, t, wa, wb);
    #pragma unroll
    for (int it = 0; it < 16; ++it) {
        unsigned* Xb = Xs[it & 1];
        unsigned* Wb = Wks[it & 1];
        storeX(Xb, t, xa, xb);
        storeW(Wb, t, wa, wb);
        __syncthreads();
        if (it < 15) {
            int nit = it + 1;
            loadX(Aseg[nit >> 3], rowbase, (nit & 7) * 16, t, xa, xb);
            loadW(Wseg[nit >> 3], (nit & 7) * 16, t, wa, wb);
        }
        mma_chunk(acc, Xb, XS_STRIDE, Wb, warpM, warpN, g, tg);
    }

    #pragma unroll
    for (int i = 0; i < 4; ++i) {
        int r0 = warpM * 64 + i * 16 + g, r1 = r0 + 8;
        const float* tap0 = taps[ts[r0]];
        const float* tap1 = taps[ts[r1]];
        #pragma unroll
        for (int j = 0; j < 4; ++j) {
            int c0 = warpN * 32 + j * 8 + tg * 2;
            float o0 = tanhf(acc[i][j].x + biass[c0]     + tap0[c0]);
            float o1 = tanhf(acc[i][j].y + biass[c0 + 1] + tap0[c0 + 1]);
            float o2 = tanhf(acc[i][j].z + biass[c0]     + tap1[c0]);
            float o3 = tanhf(acc[i][j].w + biass[c0 + 1] + tap1[c0 + 1]);
            *(float2*)(out + (rowbase + r0) * 128 + c0) = make_float2(o0, o1);
            *(float2*)(out + (rowbase + r1) * 128 + c0) = make_float2(o2, o3);
        }
    }
}

// ---------------- launch -----------------------------------------------
extern "C" void kernel_launch(void* const* d_in, const int* in_sizes, int n_in,
                              void* d_out, int out_size) {
    const float* x0   = (const float*)d_in[0];
    const float* x1   = (const float*)d_in[1];
    const float* x2   = (const float*)d_in[2];
    const int*   t0   = (const int*)  d_in[3];
    const int*   t1   = (const int*)  d_in[4];
    const int*   t2   = (const int*)  d_in[5];
    const float* A0   = (const float*)d_in[6];
    const float* A1   = (const float*)d_in[7];
    const float* E0   = (const float*)d_in[8];
    const float* E1   = (const float*)d_in[9];
    const float* W_fe = (const float*)d_in[10];
    const float* b_fe = (const float*)d_in[11];
    const float* W_x  = (const float*)d_in[12];
    const float* W_h  = (const float*)d_in[13];
    const float* W_e  = (const float*)d_in[14];
    const float* W_g  = (const float*)d_in[15];
    const float* b_g  = (const float*)d_in[16];
    const float* b_r  = (const float*)d_in[17];

    float *pooled, *h1, *Wc, *bias;
    cudaGetSymbolAddress((void**)&pooled, g_pooled);
    cudaGetSymbolAddress((void**)&h1,     g_h1);
    cudaGetSymbolAddress((void**)&Wc,     g_Wc);
    cudaGetSymbolAddress((void**)&bias,   g_bias);

    const int SMEMSZ = (128 * WS_STRIDE + 2 * 128 * XS_STRIDE + 2 * 16 * WS_STRIDE) * 4
                     + (4 * 128 + 128 + 128 + 128) * 4;   // 108544 B
    cudaFuncSetAttribute(fused_level, cudaFuncAttributeMaxDynamicSharedMemorySize, SMEMSZ);

    // fold W_fe/b_fe into per-level weights
    prep_wc<<<3 * 128, 128>>>(W_fe, W_x);
    prep_bias<<<3, 128>>>(b_fe, W_x, b_r);

    // level 2 + level 1 GNN fused: x2 -> h2 (smem) -> gate/mix -> relu GEMM -> pooled1
    fused_level<<<PB_N2 / 128, 256, SMEMSZ>>>(
        x2, t2, W_x + 2 * 132 * 128 + 128 * 128, Wc + 2 * 128 * 128, bias + 2 * 128,
        nullptr, A1, E1, W_e + 8, W_g + 128 * 128, b_g + 128, pooled);

    // h1 = tanh(x1 @ Wc1 + pooled1 @ W_h1 + bias1 + typerow)
    gemm_tanh<<<PB_N1 / 128, 256>>>(
        x1, Wc + 128 * 128, pooled, W_h + 128 * 128,
        bias + 128, W_x + 132 * 128 + 128 * 128, t1, h1);

    // level 0 GNN fused (child hidden loaded from h1)
    fused_level<<<PB_N1 / 128, 256, SMEMSZ>>>(
        nullptr, nullptr, nullptr, nullptr, nullptr,
        h1, A0, E0, W_e, W_g, b_g, pooled);

    // roots: h0 -> d_out
    gemm_tanh<<<PB_N0 / 128, 256>>>(
        x0, Wc, pooled, W_h,
        bias, W_x + 128 * 128, t0, (float*)d_out);
}